// round 2
// baseline (speedup 1.0000x reference)
#include <cuda_runtime.h>
#include <cstdint>

// ---------------------------------------------------------------------------
// RelationalKENN: unary clause enhancement + binary (edge) clause enhancement
//   up = (unary + d_unary) scatter-added with edge deltas at index1/index2
//   bp = binary + d_binary
// Output layout: [ up : n_nodes*16 floats ][ bp : n_edges*4 floats ]
// ---------------------------------------------------------------------------

#define MAX_NODES 100096  // problem fixes n_nodes = 100000

// Pre-scatter u columns 0..3 per node (only cols 0..3 feed the binary clauses).
__device__ float4 g_u03[MAX_NODES];

__device__ __forceinline__ float4 ldcs_f4(const float4* p) {
    float4 v;
    asm volatile("ld.global.cs.v4.f32 {%0,%1,%2,%3}, [%4];"
                 : "=f"(v.x), "=f"(v.y), "=f"(v.z), "=f"(v.w) : "l"(p));
    return v;
}
__device__ __forceinline__ void stcs_f4(float4* p, float4 v) {
    asm volatile("st.global.cs.v4.f32 [%0], {%1,%2,%3,%4};"
                 :: "l"(p), "f"(v.x), "f"(v.y), "f"(v.z), "f"(v.w) : "memory");
}
__device__ __forceinline__ int ldcs_i(const int* p) {
    int v;
    asm volatile("ld.global.cs.s32 %0, [%1];" : "=r"(v) : "l"(p));
    return v;
}

__global__ void __launch_bounds__(256)
unary_enhance_kernel(const float* __restrict__ unary,
                     const float* __restrict__ w,
                     float*       __restrict__ up,       // d_out up region
                     int n_nodes)
{
    int row = blockIdx.x * blockDim.x + threadIdx.x;
    if (row >= n_nodes) return;

    const float4* in4 = reinterpret_cast<const float4*>(unary) + (size_t)row * 4;
    float4 a = ldcs_f4(in4 + 0), b = ldcs_f4(in4 + 1),
           c = ldcs_f4(in4 + 2), d = ldcs_f4(in4 + 3);
    float x[16] = { a.x, a.y, a.z, a.w,  b.x, b.y, b.z, b.w,
                    c.x, c.y, c.z, c.w,  d.x, d.y, d.z, d.w };
    float dlt[16];
#pragma unroll
    for (int i = 0; i < 16; i++) dlt[i] = 0.0f;

    auto clause2 = [&](int i, int j, float wt) {
        float ea = __expf(-x[i]);
        float eb = __expf( x[j]);
        float r  = __fdividef(wt, ea + eb);
        dlt[i] -= ea * r;
        dlt[j] += eb * r;
    };
    auto clause3 = [&](int i, int j, int k, float wt) {
        float ea = __expf(-x[i]);
        float eb = __expf( x[j]);
        float ec = __expf( x[k]);
        float r  = __fdividef(wt, ea + eb + ec);
        dlt[i] -= ea * r;
        dlt[j] += eb * r;
        dlt[k] += ec * r;
    };

    float w0 = __ldg(w+0), w1 = __ldg(w+1), w2 = __ldg(w+2), w3 = __ldg(w+3);
    float w4 = __ldg(w+4), w5 = __ldg(w+5), w6 = __ldg(w+6), w7 = __ldg(w+7);

    clause2(0, 1,       w0);
    clause2(1, 2,       w1);
    clause3(2, 3, 4,    w2);
    clause2(4, 5,       w3);
    clause3(6, 7, 8,    w4);
    clause2(8, 9,       w5);
    clause3(10, 11, 12, w6);
    clause3(13, 14, 15, w7);

    float u[16];
#pragma unroll
    for (int i = 0; i < 16; i++) u[i] = x[i] + dlt[i];

    float4* o4 = reinterpret_cast<float4*>(up) + (size_t)row * 4;
    stcs_f4(o4 + 0, make_float4(u[0],  u[1],  u[2],  u[3]));
    stcs_f4(o4 + 1, make_float4(u[4],  u[5],  u[6],  u[7]));
    stcs_f4(o4 + 2, make_float4(u[8],  u[9],  u[10], u[11]));
    stcs_f4(o4 + 3, make_float4(u[12], u[13], u[14], u[15]));

    // keep this one cacheable: it's the gather target of the edge kernel
    g_u03[row] = make_float4(u[0], u[1], u[2], u[3]);
}

// Process one edge given preloaded values; emits bp store + 2 vector REDs.
__device__ __forceinline__ void edge_compute(float4 v1, float4 v2, float4 bv,
                                             float w0, float w1, float w2, float w3,
                                             float* __restrict__ up,
                                             float4* __restrict__ bp_e,
                                             int i1, int i2)
{
    float U1[4] = { v1.x, v1.y, v1.z, v1.w };
    float U2[4] = { v2.x, v2.y, v2.z, v2.w };
    float B [4] = { bv.x, bv.y, bv.z, bv.w };
    float W [4] = { w0, w1, w2, w3 };

    float du1[4], du2[4], bo[4];
#pragma unroll
    for (int k = 0; k < 4; k++) {
        float ea = __expf(-U1[k]);
        float eb = __expf(-B[k]);
        float ec = __expf( U2[k]);
        float r  = __fdividef(W[k], ea + eb + ec);
        du1[k] = -ea * r;
        bo[k]  =  B[k] - eb * r;
        du2[k] =  ec * r;
    }

    stcs_f4(bp_e, make_float4(bo[0], bo[1], bo[2], bo[3]));

    float* p1 = up + (size_t)i1 * 16;
    float* p2 = up + (size_t)i2 * 16;
    asm volatile("red.global.add.v4.f32 [%0], {%1, %2, %3, %4};"
                 :: "l"(p1), "f"(du1[0]), "f"(du1[1]), "f"(du1[2]), "f"(du1[3])
                 : "memory");
    asm volatile("red.global.add.v4.f32 [%0], {%1, %2, %3, %4};"
                 :: "l"(p2), "f"(du2[0]), "f"(du2[1]), "f"(du2[2]), "f"(du2[3])
                 : "memory");
}

__global__ void __launch_bounds__(256)
binary_enhance_kernel(const float* __restrict__ binary,
                      const int*   __restrict__ index1,
                      const int*   __restrict__ index2,
                      const float* __restrict__ w,
                      float*       __restrict__ up,      // atomic target
                      float*       __restrict__ bp,      // d_out bp region
                      int n_edges)
{
    int t  = blockIdx.x * blockDim.x + threadIdx.x;
    int e0 = t * 2;

    float w0 = __ldg(w+0), w1 = __ldg(w+1), w2 = __ldg(w+2), w3 = __ldg(w+3);

    if (e0 + 1 < n_edges) {
        // --- front-load all memory for both edges (max MLP) ---
        int i1a = ldcs_i(index1 + e0);
        int i2a = ldcs_i(index2 + e0);
        int i1b = ldcs_i(index1 + e0 + 1);
        int i2b = ldcs_i(index2 + e0 + 1);

        float4 v1a = g_u03[i1a];
        float4 v2a = g_u03[i2a];
        float4 v1b = g_u03[i1b];
        float4 v2b = g_u03[i2b];

        const float4* b4 = reinterpret_cast<const float4*>(binary);
        float4 bva = ldcs_f4(b4 + e0);
        float4 bvb = ldcs_f4(b4 + e0 + 1);

        float4* bp4 = reinterpret_cast<float4*>(bp);
        edge_compute(v1a, v2a, bva, w0, w1, w2, w3, up, bp4 + e0,     i1a, i2a);
        edge_compute(v1b, v2b, bvb, w0, w1, w2, w3, up, bp4 + e0 + 1, i1b, i2b);
    } else if (e0 < n_edges) {
        int i1 = ldcs_i(index1 + e0);
        int i2 = ldcs_i(index2 + e0);
        float4 v1 = g_u03[i1];
        float4 v2 = g_u03[i2];
        const float4* b4 = reinterpret_cast<const float4*>(binary);
        float4 bv = ldcs_f4(b4 + e0);
        float4* bp4 = reinterpret_cast<float4*>(bp);
        edge_compute(v1, v2, bv, w0, w1, w2, w3, up, bp4 + e0, i1, i2);
    }
}

extern "C" void kernel_launch(void* const* d_in, const int* in_sizes, int n_in,
                              void* d_out, int out_size)
{
    const float* unary   = (const float*)d_in[0];
    const float* binary  = (const float*)d_in[1];
    const int*   index1  = (const int*)  d_in[2];
    const int*   index2  = (const int*)  d_in[3];
    const float* uw      = (const float*)d_in[4];
    const float* bw      = (const float*)d_in[5];

    int n_nodes = in_sizes[0] / 16;
    int n_edges = in_sizes[2];

    float* up = (float*)d_out;
    float* bp = up + (size_t)n_nodes * 16;

    unary_enhance_kernel<<<(n_nodes + 255) / 256, 256>>>(unary, uw, up, n_nodes);

    int n_thr = (n_edges + 1) / 2;
    binary_enhance_kernel<<<(n_thr + 255) / 256, 256>>>(binary, index1, index2,
                                                        bw, up, bp, n_edges);
}

// round 3
// speedup vs baseline: 1.9213x; 1.9213x over previous
#include <cuda_runtime.h>
#include <cstdint>

// ---------------------------------------------------------------------------
// RelationalKENN: unary clause enhancement + binary (edge) clause enhancement
//   up = (unary + d_unary) scatter-added with edge deltas at index1/index2
//   bp = binary + d_binary
// Output layout: [ up : n_nodes*16 floats ][ bp : n_edges*4 floats ]
// ---------------------------------------------------------------------------

#define MAX_NODES 100096  // problem fixes n_nodes = 100000

// Pre-scatter u columns 0..3 per node (only cols 0..3 feed the binary clauses).
__device__ float4 g_u03[MAX_NODES];

__global__ void __launch_bounds__(256)
unary_enhance_kernel(const float* __restrict__ unary,
                     const float* __restrict__ w,
                     float*       __restrict__ up,       // d_out up region
                     int n_nodes)
{
    int row = blockIdx.x * blockDim.x + threadIdx.x;
    if (row >= n_nodes) return;

    const float4* in4 = reinterpret_cast<const float4*>(unary) + (size_t)row * 4;
    float4 a = in4[0], b = in4[1], c = in4[2], d = in4[3];
    float x[16] = { a.x, a.y, a.z, a.w,  b.x, b.y, b.z, b.w,
                    c.x, c.y, c.z, c.w,  d.x, d.y, d.z, d.w };
    float dlt[16];
#pragma unroll
    for (int i = 0; i < 16; i++) dlt[i] = 0.0f;

    auto clause2 = [&](int i, int j, float wt) {
        float ea = __expf(-x[i]);
        float eb = __expf( x[j]);
        float r  = __fdividef(wt, ea + eb);
        dlt[i] -= ea * r;
        dlt[j] += eb * r;
    };
    auto clause3 = [&](int i, int j, int k, float wt) {
        float ea = __expf(-x[i]);
        float eb = __expf( x[j]);
        float ec = __expf( x[k]);
        float r  = __fdividef(wt, ea + eb + ec);
        dlt[i] -= ea * r;
        dlt[j] += eb * r;
        dlt[k] += ec * r;
    };

    clause2(0, 1,       w[0]);
    clause2(1, 2,       w[1]);
    clause3(2, 3, 4,    w[2]);
    clause2(4, 5,       w[3]);
    clause3(6, 7, 8,    w[4]);
    clause2(8, 9,       w[5]);
    clause3(10, 11, 12, w[6]);
    clause3(13, 14, 15, w[7]);

    float u[16];
#pragma unroll
    for (int i = 0; i < 16; i++) u[i] = x[i] + dlt[i];

    float4* o4 = reinterpret_cast<float4*>(up) + (size_t)row * 4;
    o4[0] = make_float4(u[0],  u[1],  u[2],  u[3]);
    o4[1] = make_float4(u[4],  u[5],  u[6],  u[7]);
    o4[2] = make_float4(u[8],  u[9],  u[10], u[11]);
    o4[3] = make_float4(u[12], u[13], u[14], u[15]);

    g_u03[row] = make_float4(u[0], u[1], u[2], u[3]);
}

// Per-edge math + stores, given preloaded operands.
__device__ __forceinline__ void edge_compute(float4 v1, float4 v2, float4 bv,
                                             float w0, float w1, float w2, float w3,
                                             float* __restrict__ up,
                                             float4* __restrict__ bp_e,
                                             int i1, int i2)
{
    float U1[4] = { v1.x, v1.y, v1.z, v1.w };
    float U2[4] = { v2.x, v2.y, v2.z, v2.w };
    float B [4] = { bv.x, bv.y, bv.z, bv.w };
    float W [4] = { w0, w1, w2, w3 };

    float du1[4], du2[4], bo[4];
#pragma unroll
    for (int k = 0; k < 4; k++) {
        // clause k: literals (u1[k]:-1, binary[k]:-1, u2[k]:+1)
        float ea = __expf(-U1[k]);
        float eb = __expf(-B[k]);
        float ec = __expf( U2[k]);
        float r  = __fdividef(W[k], ea + eb + ec);
        du1[k] = -ea * r;
        bo[k]  =  B[k] - eb * r;
        du2[k] =  ec * r;
    }

    *bp_e = make_float4(bo[0], bo[1], bo[2], bo[3]);

    float* p1 = up + (size_t)i1 * 16;
    float* p2 = up + (size_t)i2 * 16;
    asm volatile("red.global.add.v4.f32 [%0], {%1, %2, %3, %4};"
                 :: "l"(p1), "f"(du1[0]), "f"(du1[1]), "f"(du1[2]), "f"(du1[3])
                 : "memory");
    asm volatile("red.global.add.v4.f32 [%0], {%1, %2, %3, %4};"
                 :: "l"(p2), "f"(du2[0]), "f"(du2[1]), "f"(du2[2]), "f"(du2[3])
                 : "memory");
}

// Each block owns a contiguous 512-edge chunk; thread t handles edges
// base+t and base+t+256.  Every access stays perfectly warp-coalesced
// (same wavefront count as one-edge-per-thread) while per-thread MLP doubles.
__global__ void __launch_bounds__(256)
binary_enhance_kernel(const float* __restrict__ binary,
                      const int*   __restrict__ index1,
                      const int*   __restrict__ index2,
                      const float* __restrict__ w,
                      float*       __restrict__ up,      // atomic target
                      float*       __restrict__ bp,      // d_out bp region
                      int n_edges)
{
    int base = blockIdx.x * 512 + threadIdx.x;
    int ea   = base;
    int eb   = base + 256;

    float w0 = __ldg(w+0), w1 = __ldg(w+1), w2 = __ldg(w+2), w3 = __ldg(w+3);

    const float4* b4  = reinterpret_cast<const float4*>(binary);
    float4*       bp4 = reinterpret_cast<float4*>(bp);

    bool hasA = ea < n_edges;
    bool hasB = eb < n_edges;

    if (hasA && hasB) {
        // front-load all memory for both edges (max MLP, all coalesced)
        int i1a = index1[ea];
        int i2a = index2[ea];
        int i1b = index1[eb];
        int i2b = index2[eb];

        float4 v1a = g_u03[i1a];
        float4 v2a = g_u03[i2a];
        float4 v1b = g_u03[i1b];
        float4 v2b = g_u03[i2b];

        float4 bva = b4[ea];
        float4 bvb = b4[eb];

        edge_compute(v1a, v2a, bva, w0, w1, w2, w3, up, bp4 + ea, i1a, i2a);
        edge_compute(v1b, v2b, bvb, w0, w1, w2, w3, up, bp4 + eb, i1b, i2b);
    } else if (hasA) {
        int i1 = index1[ea];
        int i2 = index2[ea];
        float4 v1 = g_u03[i1];
        float4 v2 = g_u03[i2];
        float4 bv = b4[ea];
        edge_compute(v1, v2, bv, w0, w1, w2, w3, up, bp4 + ea, i1, i2);
    }
}

extern "C" void kernel_launch(void* const* d_in, const int* in_sizes, int n_in,
                              void* d_out, int out_size)
{
    const float* unary   = (const float*)d_in[0];
    const float* binary  = (const float*)d_in[1];
    const int*   index1  = (const int*)  d_in[2];
    const int*   index2  = (const int*)  d_in[3];
    const float* uw      = (const float*)d_in[4];
    const float* bw      = (const float*)d_in[5];

    int n_nodes = in_sizes[0] / 16;
    int n_edges = in_sizes[2];

    float* up = (float*)d_out;
    float* bp = up + (size_t)n_nodes * 16;

    unary_enhance_kernel<<<(n_nodes + 255) / 256, 256>>>(unary, uw, up, n_nodes);

    int n_blocks = (n_edges + 511) / 512;
    binary_enhance_kernel<<<n_blocks, 256>>>(binary, index1, index2,
                                             bw, up, bp, n_edges);
}